// round 10
// baseline (speedup 1.0000x reference)
#include <cuda_runtime.h>
#include <cuda_fp16.h>
#include <math.h>
#include <stdint.h>

#define NV      6144
#define NFEAT   128
#define NHID    64
#define NHEAD   4
#define NCLASS  16
#define CAP     256
#define ALPHA   0.2f
#define NEGV    (-1e10f)
#define AS_STRIDE 68
#define GEMM_BLOCKS 384

// ---------------- device scratch ----------------
__device__ float  g_Weff[NFEAT * NHEAD * NHID];
__device__ __half g_Hh[(size_t)NV * NHEAD * NHID];
__device__ float  g_s[NHEAD * NV];
__device__ float  g_t[NHEAD * NV];
__device__ int    g_nbr[(size_t)NV * CAP];
__device__ int    g_cnt[NV];
__device__ float  g_H2[(size_t)NV * NCLASS];
__device__ float  g_s2[NV];
__device__ float  g_t2[NV];
__device__ int    g_gemm_done;

__device__ __forceinline__ float lrelu(float x) { return x > 0.f ? x : ALPHA * x; }
__device__ __forceinline__ float eluf(float x)  { return x > 0.f ? x : (__expf(x) - 1.f); }

// ---------------- K1: Weff (+ counter reset for this replay) ----------------
__global__ void k_weff(const float* __restrict__ W0) {
    int tid = blockIdx.x * blockDim.x + threadIdx.x;
    if (tid == 0) g_gemm_done = 0;
    if (tid >= NFEAT * NHEAD * NHID) return;
    int k = tid >> 8, C = tid & 255;
    int h = C >> 6, c = C & 63;
    const float* base = W0 + (size_t)h * 512 * 64;
    float v = 0.f;
#pragma unroll
    for (int t = 0; t < 4; t++) v += base[(t * 128 + k) * 64 + c];
    g_Weff[k * 256 + C] = v;
}

// ---------------- K2 fat kernel: GEMM blocks + (scan || spin -> attention) blocks ----------------
__global__ void __launch_bounds__(256) k_fat(const float* __restrict__ adj,
                                             const float* __restrict__ feat,
                                             const float* __restrict__ a1g,
                                             const float* __restrict__ a2g,
                                             const float* __restrict__ Wout,
                                             const float* __restrict__ a1o,
                                             const float* __restrict__ a2o) {
    __shared__ union {
        struct { float As[64 * AS_STRIDE]; float Bs[64 * 64]; } g;
        struct {
            int    s_idx[CAP];
            float  s_w[NHEAD][CAP];
            float  s_stat[NHEAD];
            float4 part[4][64];
            float  s_x2[256];
            float  part2[16][16];
            float  red[256];
            int    wsum[8];
            int    s_cnt;
        } a;
    } sm;
    int tid = threadIdx.x;
    int warp = tid >> 5, lane = tid & 31;

    if (blockIdx.x < GEMM_BLOCKS) {
        // ================= GEMM branch =================
        float* As = sm.g.As;
        float* Bs = sm.g.Bs;
        int head = blockIdx.x & 3;
        int row0 = (blockIdx.x >> 2) * 64;
        int tr = tid >> 4, tc = tid & 15;
        float acc[4][4] = {};
        const float4* feat4 = reinterpret_cast<const float4*>(feat);
        const float4* weff4 = reinterpret_cast<const float4*>(g_Weff);
        for (int kc = 0; kc < 2; kc++) {
#pragma unroll
            for (int it = 0; it < 4; it++) {
                int idx = it * 256 + tid;
                int r = idx >> 4, c4 = idx & 15;
                float4 v = feat4[(size_t)(row0 + r) * 32 + kc * 16 + c4];
                *reinterpret_cast<float4*>(&As[r * AS_STRIDE + c4 * 4]) = v;
            }
#pragma unroll
            for (int it = 0; it < 4; it++) {
                int idx = it * 256 + tid;
                int k = idx >> 4, c4 = idx & 15;
                float4 v = weff4[(size_t)(kc * 64 + k) * 64 + head * 16 + c4];
                *reinterpret_cast<float4*>(&Bs[k * 64 + c4 * 4]) = v;
            }
            __syncthreads();
#pragma unroll 4
            for (int k = 0; k < 64; k++) {
                float4 bv = *reinterpret_cast<const float4*>(&Bs[k * 64 + tc * 4]);
                float a0 = As[(tr * 4 + 0) * AS_STRIDE + k];
                float a1 = As[(tr * 4 + 1) * AS_STRIDE + k];
                float a2 = As[(tr * 4 + 2) * AS_STRIDE + k];
                float a3 = As[(tr * 4 + 3) * AS_STRIDE + k];
                acc[0][0] += a0 * bv.x; acc[0][1] += a0 * bv.y; acc[0][2] += a0 * bv.z; acc[0][3] += a0 * bv.w;
                acc[1][0] += a1 * bv.x; acc[1][1] += a1 * bv.y; acc[1][2] += a1 * bv.z; acc[1][3] += a1 * bv.w;
                acc[2][0] += a2 * bv.x; acc[2][1] += a2 * bv.y; acc[2][2] += a2 * bv.z; acc[2][3] += a2 * bv.w;
                acc[3][0] += a3 * bv.x; acc[3][1] += a3 * bv.y; acc[3][2] += a3 * bv.z; acc[3][3] += a3 * bv.w;
            }
            __syncthreads();
        }
        float a1r[4], a2r[4];
#pragma unroll
        for (int n = 0; n < 4; n++) {
            a1r[n] = __ldg(&a1g[head * 64 + tc * 4 + n]);
            a2r[n] = __ldg(&a2g[head * 64 + tc * 4 + n]);
        }
        float sp[4], tp[4];
#pragma unroll
        for (int m = 0; m < 4; m++) {
            __half2 p0 = __floats2half2_rn(acc[m][0], acc[m][1]);
            __half2 p1 = __floats2half2_rn(acc[m][2], acc[m][3]);
            uint2 st;
            st.x = *reinterpret_cast<unsigned*>(&p0);
            st.y = *reinterpret_cast<unsigned*>(&p1);
            *reinterpret_cast<uint2*>(&g_Hh[(size_t)(row0 + tr * 4 + m) * 256 + head * 64 + tc * 4]) = st;
            sp[m] = acc[m][0] * a1r[0] + acc[m][1] * a1r[1] + acc[m][2] * a1r[2] + acc[m][3] * a1r[3];
            tp[m] = acc[m][0] * a2r[0] + acc[m][1] * a2r[1] + acc[m][2] * a2r[2] + acc[m][3] * a2r[3];
        }
#pragma unroll
        for (int o = 8; o > 0; o >>= 1) {
#pragma unroll
            for (int m = 0; m < 4; m++) {
                sp[m] += __shfl_down_sync(0xffffffffu, sp[m], o, 16);
                tp[m] += __shfl_down_sync(0xffffffffu, tp[m], o, 16);
            }
        }
        if (tc == 0) {
#pragma unroll
            for (int m = 0; m < 4; m++) {
                g_s[head * NV + row0 + tr * 4 + m] = sp[m];
                g_t[head * NV + row0 + tr * 4 + m] = tp[m];
            }
        }
        // publish completion
        __threadfence();
        __syncthreads();
        if (tid == 0) atomicAdd(&g_gemm_done, 1);
        return;
    }

    // ================= attention branch =================
    int row = blockIdx.x - GEMM_BLOCKS;

    // ---- phase 0: scan adj row (independent of GEMM — overlaps with it) ----
    {
        const uint4* a4 = reinterpret_cast<const uint4*>(adj) + (size_t)row * (NV / 4);
        uint4 v[6];
#pragma unroll
        for (int it = 0; it < 6; it++) v[it] = __ldg(&a4[it * 256 + tid]);
        unsigned mask = 0;
#pragma unroll
        for (int it = 0; it < 6; it++) {
            if (v[it].x) mask |= 1u << (it * 4 + 0);
            if (v[it].y) mask |= 1u << (it * 4 + 1);
            if (v[it].z) mask |= 1u << (it * 4 + 2);
            if (v[it].w) mask |= 1u << (it * 4 + 3);
        }
        int c = __popc(mask);
        int incl = c;
#pragma unroll
        for (int o = 1; o < 32; o <<= 1) {
            int n = __shfl_up_sync(0xffffffffu, incl, o);
            if (lane >= o) incl += n;
        }
        if (lane == 31) sm.a.wsum[warp] = incl;
        __syncthreads();
        int base = 0;
#pragma unroll
        for (int w = 0; w < 8; w++) if (w < warp) base += sm.a.wsum[w];
        int pos = base + incl - c;
        while (mask) {
            int b = __ffs(mask) - 1;
            mask &= mask - 1;
            if (pos < CAP) sm.a.s_idx[pos] = (b >> 2) * 1024 + tid * 4 + (b & 3);
            pos++;
        }
        if (tid == 255) {
            int total = base + incl;
            sm.a.s_cnt = total;
            g_cnt[row] = total;
        }
    }
    __syncthreads();
    int cnt = sm.a.s_cnt;
    bool sparse = (cnt > 0 && cnt <= CAP);
    if (sparse)
        for (int k = tid; k < cnt; k += 256) g_nbr[(size_t)row * CAP + k] = sm.a.s_idx[k];

    // ---- wait for GEMM producers ----
    if (tid == 0) {
        while (*((volatile int*)&g_gemm_done) < GEMM_BLOCKS) {}
    }
    __syncthreads();
    __threadfence();

    if (sparse) {
        if (warp < 4) {
            float s_i = g_s[warp * NV + row];
            const float* tv = g_t + warp * NV;
            float mx = -INFINITY;
            for (int k = lane; k < cnt; k += 32) {
                float lv = lrelu(s_i + __ldg(&tv[sm.a.s_idx[k]]));
                sm.a.s_w[warp][k] = lv;
                mx = fmaxf(mx, lv);
            }
#pragma unroll
            for (int o = 16; o > 0; o >>= 1) mx = fmaxf(mx, __shfl_xor_sync(0xffffffffu, mx, o));
            float sum = 0.f;
            for (int k = lane; k < cnt; k += 32) {
                float e = __expf(sm.a.s_w[warp][k] - mx);
                sm.a.s_w[warp][k] = e;
                sum += e;
            }
#pragma unroll
            for (int o = 16; o > 0; o >>= 1) sum += __shfl_xor_sync(0xffffffffu, sum, o);
            if (lane == 0) sm.a.s_stat[warp] = sum;
        }
        __syncthreads();
        int q = tid >> 6, c4 = tid & 63;
        int hh = c4 >> 4;
        float4 acc = make_float4(0.f, 0.f, 0.f, 0.f);
        const uint2* hrow = reinterpret_cast<const uint2*>(g_Hh);
        int k = q;
        for (; k + 4 < cnt; k += 8) {
            float w0 = sm.a.s_w[hh][k], w1 = sm.a.s_w[hh][k + 4];
            uint2 r0 = __ldg(&hrow[(size_t)sm.a.s_idx[k] * 64 + c4]);
            uint2 r1 = __ldg(&hrow[(size_t)sm.a.s_idx[k + 4] * 64 + c4]);
            float2 f00 = __half22float2(*reinterpret_cast<__half2*>(&r0.x));
            float2 f01 = __half22float2(*reinterpret_cast<__half2*>(&r0.y));
            float2 f10 = __half22float2(*reinterpret_cast<__half2*>(&r1.x));
            float2 f11 = __half22float2(*reinterpret_cast<__half2*>(&r1.y));
            acc.x += w0 * f00.x + w1 * f10.x;
            acc.y += w0 * f00.y + w1 * f10.y;
            acc.z += w0 * f01.x + w1 * f11.x;
            acc.w += w0 * f01.y + w1 * f11.y;
        }
        for (; k < cnt; k += 4) {
            float w = sm.a.s_w[hh][k];
            uint2 raw = __ldg(&hrow[(size_t)sm.a.s_idx[k] * 64 + c4]);
            float2 f0 = __half22float2(*reinterpret_cast<__half2*>(&raw.x));
            float2 f1 = __half22float2(*reinterpret_cast<__half2*>(&raw.y));
            acc.x += w * f0.x; acc.y += w * f0.y; acc.z += w * f1.x; acc.w += w * f1.y;
        }
        sm.a.part[q][c4] = acc;
        __syncthreads();
        if (q == 0) {
            float4 p0 = sm.a.part[0][c4], p1 = sm.a.part[1][c4];
            float4 p2 = sm.a.part[2][c4], p3 = sm.a.part[3][c4];
            float S = sm.a.s_stat[hh];
            sm.a.s_x2[c4 * 4 + 0] = eluf((p0.x + p1.x + p2.x + p3.x) / S);
            sm.a.s_x2[c4 * 4 + 1] = eluf((p0.y + p1.y + p2.y + p3.y) / S);
            sm.a.s_x2[c4 * 4 + 2] = eluf((p0.z + p1.z + p2.z + p3.z) / S);
            sm.a.s_x2[c4 * 4 + 3] = eluf((p0.w + p1.w + p2.w + p3.w) / S);
        }
    } else {
        // dense fallback (rare): re-read adj row
        int g = tid >> 6, l = tid & 63;
        const float* arow = adj + (size_t)row * NV;
        float s_i = g_s[g * NV + row];
        const float* tvec = g_t + g * NV;
        float mx = -INFINITY;
        for (int j = l; j < NV; j += 64) {
            float lv = lrelu(s_i + tvec[j]);
            if (arow[j] == 0.f) lv += NEGV;
            mx = fmaxf(mx, lv);
        }
        sm.a.red[tid] = mx; __syncthreads();
        if (l < 32) {
            float m = fmaxf(sm.a.red[tid], sm.a.red[tid + 32]);
#pragma unroll
            for (int o = 16; o > 0; o >>= 1) m = fmaxf(m, __shfl_xor_sync(0xffffffffu, m, o));
            if (l == 0) sm.a.s_stat[g] = m;
        }
        __syncthreads();
        mx = sm.a.s_stat[g];
        float sum = 0.f;
        for (int j = l; j < NV; j += 64) {
            float lv = lrelu(s_i + tvec[j]);
            if (arow[j] == 0.f) lv += NEGV;
            sum += __expf(lv - mx);
        }
        __syncthreads();
        sm.a.red[tid] = sum; __syncthreads();
        if (l < 32) {
            float s = sm.a.red[tid] + sm.a.red[tid + 32];
#pragma unroll
            for (int o = 16; o > 0; o >>= 1) s += __shfl_xor_sync(0xffffffffu, s, o);
            if (l == 0) sm.a.s_stat[g] = s;
        }
        __syncthreads();
        float S = sm.a.s_stat[g];
        float acc = 0.f;
        const __half* hb = g_Hh + g * 64 + l;
        for (int j = 0; j < NV; j++) {
            float lv = lrelu(s_i + tvec[j]);
            if (arow[j] == 0.f) lv += NEGV;
            acc += __expf(lv - mx) * __half2float(hb[(size_t)j * 256]);
        }
        sm.a.s_x2[g * 64 + l] = eluf(acc / S);
    }
    __syncthreads();

    // ---- fused out-projection (Wout via L1) ----
    {
        int c = tid & 15, kq = tid >> 4;
        float acc = 0.f;
#pragma unroll
        for (int k = 0; k < 16; k++)
            acc += sm.a.s_x2[kq * 16 + k] * __ldg(&Wout[(kq * 16 + k) * 16 + c]);
        sm.a.part2[kq][c] = acc;
    }
    __syncthreads();
    if (tid < 16) {
        float h = 0.f;
#pragma unroll
        for (int w = 0; w < 16; w++) h += sm.a.part2[w][tid];
        g_H2[(size_t)row * 16 + tid] = h;
        float sa = h * __ldg(&a1o[tid]), sb = h * __ldg(&a2o[tid]);
#pragma unroll
        for (int o = 8; o > 0; o >>= 1) {
            sa += __shfl_xor_sync(0xffffu, sa, o, 16);
            sb += __shfl_xor_sync(0xffffu, sb, o, 16);
        }
        if (tid == 0) { g_s2[row] = sa; g_t2[row] = sb; }
    }
}

// ---------------- K3: output attention, warp-per-row ----------------
__global__ void __launch_bounds__(128) k_attn_out(const float* __restrict__ adj, float* __restrict__ out) {
    __shared__ float s_w[4][CAP];
    __shared__ int   s_ix[4][CAP];
    int w = threadIdx.x >> 5, lane = threadIdx.x & 31;
    int row = blockIdx.x * 4 + w;
    int cnt = g_cnt[row];
    float s_i = g_s2[row];
    bool sparse = (cnt > 0 && cnt <= CAP);

    if (sparse) {
        const int* nb = g_nbr + (size_t)row * CAP;
        float mx = -INFINITY;
        for (int k = lane; k < cnt; k += 32) {
            int ix = __ldg(&nb[k]);
            s_ix[w][k] = ix;
            float lv = lrelu(s_i + __ldg(&g_t2[ix]));
            s_w[w][k] = lv;
            mx = fmaxf(mx, lv);
        }
#pragma unroll
        for (int o = 16; o > 0; o >>= 1) mx = fmaxf(mx, __shfl_xor_sync(0xffffffffu, mx, o));
        float sum = 0.f;
        for (int k = lane; k < cnt; k += 32) {
            float e = __expf(s_w[w][k] - mx);
            s_w[w][k] = e;
            sum += e;
        }
#pragma unroll
        for (int o = 16; o > 0; o >>= 1) sum += __shfl_xor_sync(0xffffffffu, sum, o);
        __syncwarp();
        int q = lane >> 4, c = lane & 15;
        float acc = 0.f;
        int k = q;
        for (; k + 6 < cnt; k += 8) {
            float w0 = s_w[w][k],     w1 = s_w[w][k + 2];
            float w2 = s_w[w][k + 4], w3 = s_w[w][k + 6];
            int i0 = s_ix[w][k],     i1 = s_ix[w][k + 2];
            int i2 = s_ix[w][k + 4], i3 = s_ix[w][k + 6];
            float v0 = __ldg(&g_H2[(size_t)i0 * 16 + c]);
            float v1 = __ldg(&g_H2[(size_t)i1 * 16 + c]);
            float v2 = __ldg(&g_H2[(size_t)i2 * 16 + c]);
            float v3 = __ldg(&g_H2[(size_t)i3 * 16 + c]);
            acc += w0 * v0 + w1 * v1 + w2 * v2 + w3 * v3;
        }
        for (; k < cnt; k += 2)
            acc += s_w[w][k] * __ldg(&g_H2[(size_t)s_ix[w][k] * 16 + c]);
        acc += __shfl_down_sync(0xffffffffu, acc, 16);
        float v = eluf(acc / sum);
        float m16 = v;
#pragma unroll
        for (int o = 8; o > 0; o >>= 1) m16 = fmaxf(m16, __shfl_xor_sync(0xffffffffu, m16, o, 16));
        float e = __expf(v - m16);
        float se = e;
#pragma unroll
        for (int o = 8; o > 0; o >>= 1) se += __shfl_xor_sync(0xffffffffu, se, o, 16);
        if (lane < 16) out[(size_t)row * 16 + lane] = e / se;
    } else {
        const float* arow = adj + (size_t)row * NV;
        float mx = -INFINITY;
        for (int j = lane; j < NV; j += 32) {
            float lv = lrelu(s_i + g_t2[j]);
            if (arow[j] == 0.f) lv += NEGV;
            mx = fmaxf(mx, lv);
        }
#pragma unroll
        for (int o = 16; o > 0; o >>= 1) mx = fmaxf(mx, __shfl_xor_sync(0xffffffffu, mx, o));
        float sum = 0.f;
        for (int j = lane; j < NV; j += 32) {
            float lv = lrelu(s_i + g_t2[j]);
            if (arow[j] == 0.f) lv += NEGV;
            sum += __expf(lv - mx);
        }
#pragma unroll
        for (int o = 16; o > 0; o >>= 1) sum += __shfl_xor_sync(0xffffffffu, sum, o);
        int q = lane >> 4, c = lane & 15;
        float acc = 0.f;
        for (int j = q; j < NV; j += 2) {
            float lv = lrelu(s_i + g_t2[j]);
            if (arow[j] == 0.f) lv += NEGV;
            acc += __expf(lv - mx) * __ldg(&g_H2[(size_t)j * 16 + c]);
        }
        acc += __shfl_down_sync(0xffffffffu, acc, 16);
        float v = eluf(acc / sum);
        float m16 = v;
#pragma unroll
        for (int o = 8; o > 0; o >>= 1) m16 = fmaxf(m16, __shfl_xor_sync(0xffffffffu, m16, o, 16));
        float e = __expf(v - m16);
        float se = e;
#pragma unroll
        for (int o = 8; o > 0; o >>= 1) se += __shfl_xor_sync(0xffffffffu, se, o, 16);
        if (lane < 16) out[(size_t)row * 16 + lane] = e / se;
    }
}

// ---------------- launch ----------------
extern "C" void kernel_launch(void* const* d_in, const int* in_sizes, int n_in,
                              void* d_out, int out_size) {
    const float* adj  = (const float*)d_in[0];
    const float* feat = (const float*)d_in[1];
    const float* W0   = (const float*)d_in[2];
    const float* a1_0 = (const float*)d_in[3];
    const float* a2_0 = (const float*)d_in[4];
    const float* Wout = (const float*)d_in[5];
    const float* a1o  = (const float*)d_in[6];
    const float* a2o  = (const float*)d_in[7];
    float* out = (float*)d_out;

    k_weff<<<(NFEAT * NHEAD * NHID + 255) / 256, 256>>>(W0);
    k_fat<<<GEMM_BLOCKS + NV, 256>>>(adj, feat, a1_0, a2_0, Wout, a1o, a2o);
    k_attn_out<<<NV / 4, 128>>>(adj, out);
}

// round 11
// speedup vs baseline: 1.2702x; 1.2702x over previous
#include <cuda_runtime.h>
#include <cuda_fp16.h>
#include <math.h>
#include <stdint.h>

#define NV      6144
#define NFEAT   128
#define NHID    64
#define NHEAD   4
#define NCLASS  16
#define CAP     256
#define ALPHA   0.2f
#define NEGV    (-1e10f)
#define AS_STRIDE 68

// ---------------- device scratch ----------------
__device__ __half g_Hh[(size_t)NV * NHEAD * NHID];    // fp16 hidden features
__device__ float  g_s[NHEAD * NV];
__device__ float  g_t[NHEAD * NV];
__device__ int    g_nbr[(size_t)NV * CAP];
__device__ int    g_cnt[NV];
__device__ float  g_H2[(size_t)NV * NCLASS];
__device__ float  g_s2[NV];
__device__ float  g_t2[NV];

__device__ __forceinline__ float lrelu(float x) { return x > 0.f ? x : ALPHA * x; }
__device__ __forceinline__ float eluf(float x)  { return x > 0.f ? x : (__expf(x) - 1.f); }

// ---------------- K1: GEMM (Weff computed in B-load) + fused s/t, fp16 Hh ----------------
__global__ void __launch_bounds__(256) k_gemm(const float* __restrict__ feat,
                                              const float* __restrict__ W0,
                                              const float* __restrict__ a1g,
                                              const float* __restrict__ a2g) {
    __shared__ float As[64 * AS_STRIDE];
    __shared__ float Bs[64 * 64];
    int tid = threadIdx.x;
    int head = blockIdx.x & 3;
    int row0 = (blockIdx.x >> 2) * 64;
    int tr = tid >> 4, tc = tid & 15;
    float acc[4][4] = {};
    const float4* feat4 = reinterpret_cast<const float4*>(feat);
    const float4* w04 = reinterpret_cast<const float4*>(W0 + (size_t)head * 512 * 64);
    for (int kc = 0; kc < 2; kc++) {
#pragma unroll
        for (int it = 0; it < 4; it++) {
            int idx = it * 256 + tid;
            int r = idx >> 4, c4 = idx & 15;
            float4 v = feat4[(size_t)(row0 + r) * 32 + kc * 16 + c4];
            *reinterpret_cast<float4*>(&As[r * AS_STRIDE + c4 * 4]) = v;
        }
        // B tile: Weff[k][c] = sum_t W0[h][(t*128 + kc*64 + k)][c]
#pragma unroll
        for (int it = 0; it < 4; it++) {
            int idx = it * 256 + tid;
            int k = idx >> 4, c4 = idx & 15;
            int krow = kc * 64 + k;
            float4 b = make_float4(0.f, 0.f, 0.f, 0.f);
#pragma unroll
            for (int t = 0; t < 4; t++) {
                float4 v = __ldg(&w04[(size_t)(t * 128 + krow) * 16 + c4]);
                b.x += v.x; b.y += v.y; b.z += v.z; b.w += v.w;
            }
            *reinterpret_cast<float4*>(&Bs[k * 64 + c4 * 4]) = b;
        }
        __syncthreads();
#pragma unroll 4
        for (int k = 0; k < 64; k++) {
            float4 bv = *reinterpret_cast<const float4*>(&Bs[k * 64 + tc * 4]);
            float a0 = As[(tr * 4 + 0) * AS_STRIDE + k];
            float a1 = As[(tr * 4 + 1) * AS_STRIDE + k];
            float a2 = As[(tr * 4 + 2) * AS_STRIDE + k];
            float a3 = As[(tr * 4 + 3) * AS_STRIDE + k];
            acc[0][0] += a0 * bv.x; acc[0][1] += a0 * bv.y; acc[0][2] += a0 * bv.z; acc[0][3] += a0 * bv.w;
            acc[1][0] += a1 * bv.x; acc[1][1] += a1 * bv.y; acc[1][2] += a1 * bv.z; acc[1][3] += a1 * bv.w;
            acc[2][0] += a2 * bv.x; acc[2][1] += a2 * bv.y; acc[2][2] += a2 * bv.z; acc[2][3] += a2 * bv.w;
            acc[3][0] += a3 * bv.x; acc[3][1] += a3 * bv.y; acc[3][2] += a3 * bv.z; acc[3][3] += a3 * bv.w;
        }
        __syncthreads();
    }
    float a1r[4], a2r[4];
#pragma unroll
    for (int n = 0; n < 4; n++) {
        a1r[n] = __ldg(&a1g[head * 64 + tc * 4 + n]);
        a2r[n] = __ldg(&a2g[head * 64 + tc * 4 + n]);
    }
    float sp[4], tp[4];
#pragma unroll
    for (int m = 0; m < 4; m++) {
        __half2 p0 = __floats2half2_rn(acc[m][0], acc[m][1]);
        __half2 p1 = __floats2half2_rn(acc[m][2], acc[m][3]);
        uint2 st;
        st.x = *reinterpret_cast<unsigned*>(&p0);
        st.y = *reinterpret_cast<unsigned*>(&p1);
        *reinterpret_cast<uint2*>(&g_Hh[(size_t)(row0 + tr * 4 + m) * 256 + head * 64 + tc * 4]) = st;
        sp[m] = acc[m][0] * a1r[0] + acc[m][1] * a1r[1] + acc[m][2] * a1r[2] + acc[m][3] * a1r[3];
        tp[m] = acc[m][0] * a2r[0] + acc[m][1] * a2r[1] + acc[m][2] * a2r[2] + acc[m][3] * a2r[3];
    }
#pragma unroll
    for (int o = 8; o > 0; o >>= 1) {
#pragma unroll
        for (int m = 0; m < 4; m++) {
            sp[m] += __shfl_down_sync(0xffffffffu, sp[m], o, 16);
            tp[m] += __shfl_down_sync(0xffffffffu, tp[m], o, 16);
        }
    }
    if (tc == 0) {
#pragma unroll
        for (int m = 0; m < 4; m++) {
            g_s[head * NV + row0 + tr * 4 + m] = sp[m];
            g_t[head * NV + row0 + tr * 4 + m] = tp[m];
        }
    }
}

// ---------------- K2: FUSED adj-scan + hidden attention + out-proj ----------------
__global__ void __launch_bounds__(256) k_attn_hidden(const float* __restrict__ adj,
                                                     const float* __restrict__ Wout,
                                                     const float* __restrict__ a1o,
                                                     const float* __restrict__ a2o) {
    int row = blockIdx.x;
    int tid = threadIdx.x;
    int warp = tid >> 5, lane = tid & 31;
    __shared__ int    s_idx[CAP];
    __shared__ float  s_w[NHEAD][CAP];
    __shared__ float  s_stat[NHEAD];
    __shared__ float4 part[4][64];
    __shared__ float  s_x2[256];
    __shared__ float  part2[16][16];
    __shared__ float  red[256];
    __shared__ int    wsum[8];
    __shared__ int    s_cnt;

    // ---- phase 0: scan this row of adj, compact neighbors into smem ----
    {
        const uint4* a4 = reinterpret_cast<const uint4*>(adj) + (size_t)row * (NV / 4);
        uint4 v[6];
#pragma unroll
        for (int it = 0; it < 6; it++) v[it] = __ldg(&a4[it * 256 + tid]);
        unsigned mask = 0;
#pragma unroll
        for (int it = 0; it < 6; it++) {
            if (v[it].x) mask |= 1u << (it * 4 + 0);
            if (v[it].y) mask |= 1u << (it * 4 + 1);
            if (v[it].z) mask |= 1u << (it * 4 + 2);
            if (v[it].w) mask |= 1u << (it * 4 + 3);
        }
        int c = __popc(mask);
        int incl = c;
#pragma unroll
        for (int o = 1; o < 32; o <<= 1) {
            int n = __shfl_up_sync(0xffffffffu, incl, o);
            if (lane >= o) incl += n;
        }
        if (lane == 31) wsum[warp] = incl;
        __syncthreads();
        int base = 0;
#pragma unroll
        for (int w = 0; w < 8; w++) if (w < warp) base += wsum[w];
        int pos = base + incl - c;
        while (mask) {
            int b = __ffs(mask) - 1;
            mask &= mask - 1;
            if (pos < CAP) s_idx[pos] = (b >> 2) * 1024 + tid * 4 + (b & 3);
            pos++;
        }
        if (tid == 255) {
            int total = base + incl;
            s_cnt = total;
            g_cnt[row] = total;
        }
    }
    __syncthreads();
    int cnt = s_cnt;
    bool sparse = (cnt > 0 && cnt <= CAP);
    if (sparse)
        for (int k = tid; k < cnt; k += 256) g_nbr[(size_t)row * CAP + k] = s_idx[k];

    if (sparse) {
        // warp-per-head softmax weights
        if (warp < 4) {
            float s_i = g_s[warp * NV + row];
            const float* tv = g_t + warp * NV;
            float mx = -INFINITY;
            for (int k = lane; k < cnt; k += 32) {
                float lv = lrelu(s_i + __ldg(&tv[s_idx[k]]));
                s_w[warp][k] = lv;
                mx = fmaxf(mx, lv);
            }
#pragma unroll
            for (int o = 16; o > 0; o >>= 1) mx = fmaxf(mx, __shfl_xor_sync(0xffffffffu, mx, o));
            float sum = 0.f;
            for (int k = lane; k < cnt; k += 32) {
                float e = __expf(s_w[warp][k] - mx);
                s_w[warp][k] = e;
                sum += e;
            }
#pragma unroll
            for (int o = 16; o > 0; o >>= 1) sum += __shfl_xor_sync(0xffffffffu, sum, o);
            if (lane == 0) s_stat[warp] = sum;
        }
        __syncthreads();
        // gather: q = neighbor phase (4), c4 = 8-byte chunk of 256-col fp16 row; 2-wide unroll
        int q = tid >> 6, c4 = tid & 63;
        int hh = c4 >> 4;
        float4 acc = make_float4(0.f, 0.f, 0.f, 0.f);
        const uint2* hrow = reinterpret_cast<const uint2*>(g_Hh);
        int k = q;
        for (; k + 4 < cnt; k += 8) {
            float w0 = s_w[hh][k], w1 = s_w[hh][k + 4];
            uint2 r0 = __ldg(&hrow[(size_t)s_idx[k] * 64 + c4]);
            uint2 r1 = __ldg(&hrow[(size_t)s_idx[k + 4] * 64 + c4]);
            float2 f00 = __half22float2(*reinterpret_cast<__half2*>(&r0.x));
            float2 f01 = __half22float2(*reinterpret_cast<__half2*>(&r0.y));
            float2 f10 = __half22float2(*reinterpret_cast<__half2*>(&r1.x));
            float2 f11 = __half22float2(*reinterpret_cast<__half2*>(&r1.y));
            acc.x += w0 * f00.x + w1 * f10.x;
            acc.y += w0 * f00.y + w1 * f10.y;
            acc.z += w0 * f01.x + w1 * f11.x;
            acc.w += w0 * f01.y + w1 * f11.y;
        }
        for (; k < cnt; k += 4) {
            float w = s_w[hh][k];
            uint2 raw = __ldg(&hrow[(size_t)s_idx[k] * 64 + c4]);
            float2 f0 = __half22float2(*reinterpret_cast<__half2*>(&raw.x));
            float2 f1 = __half22float2(*reinterpret_cast<__half2*>(&raw.y));
            acc.x += w * f0.x; acc.y += w * f0.y; acc.z += w * f1.x; acc.w += w * f1.y;
        }
        part[q][c4] = acc;
        __syncthreads();
        if (q == 0) {
            float4 p0 = part[0][c4], p1 = part[1][c4], p2 = part[2][c4], p3 = part[3][c4];
            float S = s_stat[hh];
            s_x2[c4 * 4 + 0] = eluf((p0.x + p1.x + p2.x + p3.x) / S);
            s_x2[c4 * 4 + 1] = eluf((p0.y + p1.y + p2.y + p3.y) / S);
            s_x2[c4 * 4 + 2] = eluf((p0.z + p1.z + p2.z + p3.z) / S);
            s_x2[c4 * 4 + 3] = eluf((p0.w + p1.w + p2.w + p3.w) / S);
        }
    } else {
        // dense fallback (rare): re-read adj row
        int g = tid >> 6, l = tid & 63;
        const float* arow = adj + (size_t)row * NV;
        float s_i = g_s[g * NV + row];
        const float* tvec = g_t + g * NV;
        float mx = -INFINITY;
        for (int j = l; j < NV; j += 64) {
            float lv = lrelu(s_i + tvec[j]);
            if (arow[j] == 0.f) lv += NEGV;
            mx = fmaxf(mx, lv);
        }
        red[tid] = mx; __syncthreads();
        if (l < 32) {
            float m = fmaxf(red[tid], red[tid + 32]);
#pragma unroll
            for (int o = 16; o > 0; o >>= 1) m = fmaxf(m, __shfl_xor_sync(0xffffffffu, m, o));
            if (l == 0) s_stat[g] = m;
        }
        __syncthreads();
        mx = s_stat[g];
        float sum = 0.f;
        for (int j = l; j < NV; j += 64) {
            float lv = lrelu(s_i + tvec[j]);
            if (arow[j] == 0.f) lv += NEGV;
            sum += __expf(lv - mx);
        }
        __syncthreads();
        red[tid] = sum; __syncthreads();
        if (l < 32) {
            float s = red[tid] + red[tid + 32];
#pragma unroll
            for (int o = 16; o > 0; o >>= 1) s += __shfl_xor_sync(0xffffffffu, s, o);
            if (l == 0) s_stat[g] = s;
        }
        __syncthreads();
        float S = s_stat[g];
        float acc = 0.f;
        const __half* hb = g_Hh + g * 64 + l;
        for (int j = 0; j < NV; j++) {
            float lv = lrelu(s_i + tvec[j]);
            if (arow[j] == 0.f) lv += NEGV;
            acc += __expf(lv - mx) * __half2float(hb[(size_t)j * 256]);
        }
        s_x2[g * 64 + l] = eluf(acc / S);
    }
    __syncthreads();

    // ---- fused out-projection (Wout via L1) ----
    {
        int c = tid & 15, kq = tid >> 4;
        float acc = 0.f;
#pragma unroll
        for (int k = 0; k < 16; k++)
            acc += s_x2[kq * 16 + k] * __ldg(&Wout[(kq * 16 + k) * 16 + c]);
        part2[kq][c] = acc;
    }
    __syncthreads();
    if (tid < 16) {
        float h = 0.f;
#pragma unroll
        for (int w = 0; w < 16; w++) h += part2[w][tid];
        g_H2[(size_t)row * 16 + tid] = h;
        float sa = h * __ldg(&a1o[tid]), sb = h * __ldg(&a2o[tid]);
#pragma unroll
        for (int o = 8; o > 0; o >>= 1) {
            sa += __shfl_xor_sync(0xffffu, sa, o, 16);
            sb += __shfl_xor_sync(0xffffu, sb, o, 16);
        }
        if (tid == 0) { g_s2[row] = sa; g_t2[row] = sb; }
    }
}

// ---------------- K3: output attention, warp-per-row ----------------
__global__ void __launch_bounds__(128) k_attn_out(const float* __restrict__ adj, float* __restrict__ out) {
    __shared__ float s_w[4][CAP];
    __shared__ int   s_ix[4][CAP];
    int w = threadIdx.x >> 5, lane = threadIdx.x & 31;
    int row = blockIdx.x * 4 + w;
    int cnt = g_cnt[row];
    float s_i = g_s2[row];
    bool sparse = (cnt > 0 && cnt <= CAP);

    if (sparse) {
        const int* nb = g_nbr + (size_t)row * CAP;
        float mx = -INFINITY;
        for (int k = lane; k < cnt; k += 32) {
            int ix = __ldg(&nb[k]);
            s_ix[w][k] = ix;
            float lv = lrelu(s_i + __ldg(&g_t2[ix]));
            s_w[w][k] = lv;
            mx = fmaxf(mx, lv);
        }
#pragma unroll
        for (int o = 16; o > 0; o >>= 1) mx = fmaxf(mx, __shfl_xor_sync(0xffffffffu, mx, o));
        float sum = 0.f;
        for (int k = lane; k < cnt; k += 32) {
            float e = __expf(s_w[w][k] - mx);
            s_w[w][k] = e;
            sum += e;
        }
#pragma unroll
        for (int o = 16; o > 0; o >>= 1) sum += __shfl_xor_sync(0xffffffffu, sum, o);
        __syncwarp();
        int q = lane >> 4, c = lane & 15;
        float acc = 0.f;
        int k = q;
        for (; k + 6 < cnt; k += 8) {
            float w0 = s_w[w][k],     w1 = s_w[w][k + 2];
            float w2 = s_w[w][k + 4], w3 = s_w[w][k + 6];
            int i0 = s_ix[w][k],     i1 = s_ix[w][k + 2];
            int i2 = s_ix[w][k + 4], i3 = s_ix[w][k + 6];
            float v0 = __ldg(&g_H2[(size_t)i0 * 16 + c]);
            float v1 = __ldg(&g_H2[(size_t)i1 * 16 + c]);
            float v2 = __ldg(&g_H2[(size_t)i2 * 16 + c]);
            float v3 = __ldg(&g_H2[(size_t)i3 * 16 + c]);
            acc += w0 * v0 + w1 * v1 + w2 * v2 + w3 * v3;
        }
        for (; k < cnt; k += 2)
            acc += s_w[w][k] * __ldg(&g_H2[(size_t)s_ix[w][k] * 16 + c]);
        acc += __shfl_down_sync(0xffffffffu, acc, 16);
        float v = eluf(acc / sum);
        float m16 = v;
#pragma unroll
        for (int o = 8; o > 0; o >>= 1) m16 = fmaxf(m16, __shfl_xor_sync(0xffffffffu, m16, o, 16));
        float e = __expf(v - m16);
        float se = e;
#pragma unroll
        for (int o = 8; o > 0; o >>= 1) se += __shfl_xor_sync(0xffffffffu, se, o, 16);
        if (lane < 16) out[(size_t)row * 16 + lane] = e / se;
    } else {
        const float* arow = adj + (size_t)row * NV;
        float mx = -INFINITY;
        for (int j = lane; j < NV; j += 32) {
            float lv = lrelu(s_i + g_t2[j]);
            if (arow[j] == 0.f) lv += NEGV;
            mx = fmaxf(mx, lv);
        }
#pragma unroll
        for (int o = 16; o > 0; o >>= 1) mx = fmaxf(mx, __shfl_xor_sync(0xffffffffu, mx, o));
        float sum = 0.f;
        for (int j = lane; j < NV; j += 32) {
            float lv = lrelu(s_i + g_t2[j]);
            if (arow[j] == 0.f) lv += NEGV;
            sum += __expf(lv - mx);
        }
#pragma unroll
        for (int o = 16; o > 0; o >>= 1) sum += __shfl_xor_sync(0xffffffffu, sum, o);
        int q = lane >> 4, c = lane & 15;
        float acc = 0.f;
        for (int j = q; j < NV; j += 2) {
            float lv = lrelu(s_i + g_t2[j]);
            if (arow[j] == 0.f) lv += NEGV;
            acc += __expf(lv - mx) * __ldg(&g_H2[(size_t)j * 16 + c]);
        }
        acc += __shfl_down_sync(0xffffffffu, acc, 16);
        float v = eluf(acc / sum);
        float m16 = v;
#pragma unroll
        for (int o = 8; o > 0; o >>= 1) m16 = fmaxf(m16, __shfl_xor_sync(0xffffffffu, m16, o, 16));
        float e = __expf(v - m16);
        float se = e;
#pragma unroll
        for (int o = 8; o > 0; o >>= 1) se += __shfl_xor_sync(0xffffffffu, se, o, 16);
        if (lane < 16) out[(size_t)row * 16 + lane] = e / se;
    }
}

// ---------------- launch ----------------
extern "C" void kernel_launch(void* const* d_in, const int* in_sizes, int n_in,
                              void* d_out, int out_size) {
    const float* adj  = (const float*)d_in[0];
    const float* feat = (const float*)d_in[1];
    const float* W0   = (const float*)d_in[2];
    const float* a1_0 = (const float*)d_in[3];
    const float* a2_0 = (const float*)d_in[4];
    const float* Wout = (const float*)d_in[5];
    const float* a1o  = (const float*)d_in[6];
    const float* a2o  = (const float*)d_in[7];
    float* out = (float*)d_out;

    k_gemm<<<(NV / 64) * NHEAD, 256>>>(feat, W0, a1_0, a2_0);   // Weff folded into B-load
    k_attn_hidden<<<NV, 256>>>(adj, Wout, a1o, a2o);            // adj scan fused
    k_attn_out<<<NV / 4, 128>>>(adj, out);
}

// round 12
// speedup vs baseline: 1.4063x; 1.1072x over previous
#include <cuda_runtime.h>
#include <cuda_fp16.h>
#include <mma.h>
#include <math.h>
#include <stdint.h>

using namespace nvcuda;

#define NV      6144
#define NFEAT   128
#define NHID    64
#define NHEAD   4
#define NCLASS  16
#define CAP     256
#define ALPHA   0.2f
#define NEGV    (-1e10f)
#define LDA     136   // 128 + 8 halfs pad (mult of 8)
#define LDB     72    // 64 + 8 halfs pad

// ---------------- device scratch ----------------
__device__ __half g_Hh[(size_t)NV * NHEAD * NHID];    // fp16 hidden features
__device__ float  g_s[NHEAD * NV];
__device__ float  g_t[NHEAD * NV];
__device__ int    g_nbr[(size_t)NV * CAP];
__device__ int    g_cnt[NV];
__device__ float  g_H2[(size_t)NV * NCLASS];
__device__ float  g_s2[NV];
__device__ float  g_t2[NV];

__device__ __forceinline__ float lrelu(float x) { return x > 0.f ? x : ALPHA * x; }
__device__ __forceinline__ float eluf(float x)  { return x > 0.f ? x : (__expf(x) - 1.f); }

// ---------------- K1: tensor-core GEMM (Weff folded in B-load) + fused s/t ----------------
__global__ void __launch_bounds__(256) k_gemm(const float* __restrict__ feat,
                                              const float* __restrict__ W0,
                                              const float* __restrict__ a1g,
                                              const float* __restrict__ a2g) {
    __shared__ __align__(16) __half AsH[64 * LDA];   // 17408 B ; later overlaid by C (16384 B)
    __shared__ __align__(16) __half BsH[128 * LDB];  // 18432 B
    float* Cs = reinterpret_cast<float*>(AsH);
    int tid = threadIdx.x;
    int head = blockIdx.x & 3;
    int row0 = (blockIdx.x >> 2) * 64;
    const float4* feat4 = reinterpret_cast<const float4*>(feat);
    const float4* w04 = reinterpret_cast<const float4*>(W0 + (size_t)head * 512 * 64);

    // ---- load A: feat tile 64x128, convert fp32 -> fp16 in-register ----
#pragma unroll
    for (int it = 0; it < 8; it++) {
        int idx = it * 256 + tid;        // 2048 float4-groups
        int r = idx >> 5, c4 = idx & 31; // 32 groups per 128-col row
        float4 v = feat4[(size_t)(row0 + r) * 32 + c4];
        __half2 h0 = __floats2half2_rn(v.x, v.y);
        __half2 h1 = __floats2half2_rn(v.z, v.w);
        uint2 st;
        st.x = *reinterpret_cast<unsigned*>(&h0);
        st.y = *reinterpret_cast<unsigned*>(&h1);
        *reinterpret_cast<uint2*>(&AsH[r * LDA + c4 * 4]) = st;
    }
    // ---- load B: Weff[k][c] = sum_t W0[h][t*128+k][c], fp32 sum -> fp16 ----
#pragma unroll
    for (int it = 0; it < 8; it++) {
        int idx = it * 256 + tid;        // 2048 float4-groups (128 x 16)
        int k = idx >> 4, c4 = idx & 15;
        float4 b = make_float4(0.f, 0.f, 0.f, 0.f);
#pragma unroll
        for (int t = 0; t < 4; t++) {
            float4 v = __ldg(&w04[(size_t)(t * 128 + k) * 16 + c4]);
            b.x += v.x; b.y += v.y; b.z += v.z; b.w += v.w;
        }
        __half2 h0 = __floats2half2_rn(b.x, b.y);
        __half2 h1 = __floats2half2_rn(b.z, b.w);
        uint2 st;
        st.x = *reinterpret_cast<unsigned*>(&h0);
        st.y = *reinterpret_cast<unsigned*>(&h1);
        *reinterpret_cast<uint2*>(&BsH[k * LDB + c4 * 4]) = st;
    }
    __syncthreads();

    // ---- wmma: 8 warps; warp w -> rows (w>>1)*16, cols (w&1)*32 .. +31 ----
    int warp = tid >> 5;
    int wr = (warp >> 1) * 16;
    int wc = (warp & 1) * 32;
    wmma::fragment<wmma::accumulator, 16, 16, 16, float> c0, c1;
    wmma::fill_fragment(c0, 0.f);
    wmma::fill_fragment(c1, 0.f);
#pragma unroll
    for (int k0 = 0; k0 < 128; k0 += 16) {
        wmma::fragment<wmma::matrix_a, 16, 16, 16, __half, wmma::row_major> a;
        wmma::fragment<wmma::matrix_b, 16, 16, 16, __half, wmma::row_major> b0, b1;
        wmma::load_matrix_sync(a, &AsH[wr * LDA + k0], LDA);
        wmma::load_matrix_sync(b0, &BsH[k0 * LDB + wc], LDB);
        wmma::load_matrix_sync(b1, &BsH[k0 * LDB + wc + 16], LDB);
        wmma::mma_sync(c0, a, b0, c0);
        wmma::mma_sync(c1, a, b1, c1);
    }
    __syncthreads();   // everyone done reading AsH before C overlays it
    wmma::store_matrix_sync(&Cs[wr * 64 + wc], c0, 64, wmma::mem_row_major);
    wmma::store_matrix_sync(&Cs[wr * 64 + wc + 16], c1, 64, wmma::mem_row_major);
    __syncthreads();

    // ---- epilogue: fp16 store of H + fused s/t dots (from fp32 C) ----
    int r = tid >> 2, q = tid & 3;       // row 0..63, col-quarter 0..3
    const float* crow = &Cs[r * 64 + q * 16];
    float sa = 0.f, sb = 0.f;
    __half hbuf[16];
#pragma unroll
    for (int c = 0; c < 16; c++) {
        float v = crow[c];
        hbuf[c] = __float2half_rn(v);
        sa += v * __ldg(&a1g[head * 64 + q * 16 + c]);
        sb += v * __ldg(&a2g[head * 64 + q * 16 + c]);
    }
    uint4* dst = reinterpret_cast<uint4*>(&g_Hh[(size_t)(row0 + r) * 256 + head * 64 + q * 16]);
    const uint4* src = reinterpret_cast<const uint4*>(hbuf);
    dst[0] = src[0];
    dst[1] = src[1];
    sa += __shfl_down_sync(0xffffffffu, sa, 2, 4);
    sa += __shfl_down_sync(0xffffffffu, sa, 1, 4);
    sb += __shfl_down_sync(0xffffffffu, sb, 2, 4);
    sb += __shfl_down_sync(0xffffffffu, sb, 1, 4);
    if (q == 0) {
        g_s[head * NV + row0 + r] = sa;
        g_t[head * NV + row0 + r] = sb;
    }
}

// ---------------- K2: FUSED adj-scan + hidden attention + out-proj ----------------
__global__ void __launch_bounds__(256) k_attn_hidden(const float* __restrict__ adj,
                                                     const float* __restrict__ Wout,
                                                     const float* __restrict__ a1o,
                                                     const float* __restrict__ a2o) {
    int row = blockIdx.x;
    int tid = threadIdx.x;
    int warp = tid >> 5, lane = tid & 31;
    __shared__ int    s_idx[CAP];
    __shared__ float  s_w[NHEAD][CAP];
    __shared__ float  s_stat[NHEAD];
    __shared__ float4 part[4][64];
    __shared__ float  s_x2[256];
    __shared__ float  part2[16][16];
    __shared__ float  red[256];
    __shared__ int    wsum[8];
    __shared__ int    s_cnt;

    // ---- phase 0: scan this row of adj, compact neighbors into smem ----
    {
        const uint4* a4 = reinterpret_cast<const uint4*>(adj) + (size_t)row * (NV / 4);
        uint4 v[6];
#pragma unroll
        for (int it = 0; it < 6; it++) v[it] = __ldg(&a4[it * 256 + tid]);
        unsigned mask = 0;
#pragma unroll
        for (int it = 0; it < 6; it++) {
            if (v[it].x) mask |= 1u << (it * 4 + 0);
            if (v[it].y) mask |= 1u << (it * 4 + 1);
            if (v[it].z) mask |= 1u << (it * 4 + 2);
            if (v[it].w) mask |= 1u << (it * 4 + 3);
        }
        int c = __popc(mask);
        int incl = c;
#pragma unroll
        for (int o = 1; o < 32; o <<= 1) {
            int n = __shfl_up_sync(0xffffffffu, incl, o);
            if (lane >= o) incl += n;
        }
        if (lane == 31) wsum[warp] = incl;
        __syncthreads();
        int base = 0;
#pragma unroll
        for (int w = 0; w < 8; w++) if (w < warp) base += wsum[w];
        int pos = base + incl - c;
        while (mask) {
            int b = __ffs(mask) - 1;
            mask &= mask - 1;
            if (pos < CAP) s_idx[pos] = (b >> 2) * 1024 + tid * 4 + (b & 3);
            pos++;
        }
        if (tid == 255) {
            int total = base + incl;
            s_cnt = total;
            g_cnt[row] = total;
        }
    }
    __syncthreads();
    int cnt = s_cnt;
    bool sparse = (cnt > 0 && cnt <= CAP);
    if (sparse)
        for (int k = tid; k < cnt; k += 256) g_nbr[(size_t)row * CAP + k] = s_idx[k];

    if (sparse) {
        if (warp < 4) {
            float s_i = g_s[warp * NV + row];
            const float* tv = g_t + warp * NV;
            float mx = -INFINITY;
            for (int k = lane; k < cnt; k += 32) {
                float lv = lrelu(s_i + __ldg(&tv[s_idx[k]]));
                s_w[warp][k] = lv;
                mx = fmaxf(mx, lv);
            }
#pragma unroll
            for (int o = 16; o > 0; o >>= 1) mx = fmaxf(mx, __shfl_xor_sync(0xffffffffu, mx, o));
            float sum = 0.f;
            for (int k = lane; k < cnt; k += 32) {
                float e = __expf(s_w[warp][k] - mx);
                s_w[warp][k] = e;
                sum += e;
            }
#pragma unroll
            for (int o = 16; o > 0; o >>= 1) sum += __shfl_xor_sync(0xffffffffu, sum, o);
            if (lane == 0) s_stat[warp] = sum;
        }
        __syncthreads();
        int q = tid >> 6, c4 = tid & 63;
        int hh = c4 >> 4;
        float4 acc = make_float4(0.f, 0.f, 0.f, 0.f);
        const uint2* hrow = reinterpret_cast<const uint2*>(g_Hh);
        int k = q;
        for (; k + 4 < cnt; k += 8) {
            float w0 = s_w[hh][k], w1 = s_w[hh][k + 4];
            uint2 r0 = __ldg(&hrow[(size_t)s_idx[k] * 64 + c4]);
            uint2 r1 = __ldg(&hrow[(size_t)s_idx[k + 4] * 64 + c4]);
            float2 f00 = __half22float2(*reinterpret_cast<__half2*>(&r0.x));
            float2 f01 = __half22float2(*reinterpret_cast<__half2*>(&r0.y));
            float2 f10 = __half22float2(*reinterpret_cast<__half2*>(&r1.x));
            float2 f11 = __half22float2(*reinterpret_cast<__half2*>(&r1.y));
            acc.x += w0 * f00.x + w1 * f10.x;
            acc.y += w0 * f00.y + w1 * f10.y;
            acc.z += w0 * f01.x + w1 * f11.x;
            acc.w += w0 * f01.y + w1 * f11.y;
        }
        for (; k < cnt; k += 4) {
            float w = s_w[hh][k];
            uint2 raw = __ldg(&hrow[(size_t)s_idx[k] * 64 + c4]);
            float2 f0 = __half22float2(*reinterpret_cast<__half2*>(&raw.x));
            float2 f1 = __half22float2(*reinterpret_cast<__half2*>(&raw.y));
            acc.x += w * f0.x; acc.y += w * f0.y; acc.z += w * f1.x; acc.w += w * f1.y;
        }
        part[q][c4] = acc;
        __syncthreads();
        if (q == 0) {
            float4 p0 = part[0][c4], p1 = part[1][c4], p2 = part[2][c4], p3 = part[3][c4];
            float S = s_stat[hh];
            s_x2[c4 * 4 + 0] = eluf((p0.x + p1.x + p2.x + p3.x) / S);
            s_x2[c4 * 4 + 1] = eluf((p0.y + p1.y + p2.y + p3.y) / S);
            s_x2[c4 * 4 + 2] = eluf((p0.z + p1.z + p2.z + p3.z) / S);
            s_x2[c4 * 4 + 3] = eluf((p0.w + p1.w + p2.w + p3.w) / S);
        }
    } else {
        int g = tid >> 6, l = tid & 63;
        const float* arow = adj + (size_t)row * NV;
        float s_i = g_s[g * NV + row];
        const float* tvec = g_t + g * NV;
        float mx = -INFINITY;
        for (int j = l; j < NV; j += 64) {
            float lv = lrelu(s_i + tvec[j]);
            if (arow[j] == 0.f) lv += NEGV;
            mx = fmaxf(mx, lv);
        }
        red[tid] = mx; __syncthreads();
        if (l < 32) {
            float m = fmaxf(red[tid], red[tid + 32]);
#pragma unroll
            for (int o = 16; o > 0; o >>= 1) m = fmaxf(m, __shfl_xor_sync(0xffffffffu, m, o));
            if (l == 0) s_stat[g] = m;
        }
        __syncthreads();
        mx = s_stat[g];
        float sum = 0.f;
        for (int j = l; j < NV; j += 64) {
            float lv = lrelu(s_i + tvec[j]);
            if (arow[j] == 0.f) lv += NEGV;
            sum += __expf(lv - mx);
        }
        __syncthreads();
        red[tid] = sum; __syncthreads();
        if (l < 32) {
            float s = red[tid] + red[tid + 32];
#pragma unroll
            for (int o = 16; o > 0; o >>= 1) s += __shfl_xor_sync(0xffffffffu, s, o);
            if (l == 0) s_stat[g] = s;
        }
        __syncthreads();
        float S = s_stat[g];
        float acc = 0.f;
        const __half* hb = g_Hh + g * 64 + l;
        for (int j = 0; j < NV; j++) {
            float lv = lrelu(s_i + tvec[j]);
            if (arow[j] == 0.f) lv += NEGV;
            acc += __expf(lv - mx) * __half2float(hb[(size_t)j * 256]);
        }
        s_x2[g * 64 + l] = eluf(acc / S);
    }
    __syncthreads();

    // ---- fused out-projection (Wout via L1) ----
    {
        int c = tid & 15, kq = tid >> 4;
        float acc = 0.f;
#pragma unroll
        for (int k = 0; k < 16; k++)
            acc += s_x2[kq * 16 + k] * __ldg(&Wout[(kq * 16 + k) * 16 + c]);
        part2[kq][c] = acc;
    }
    __syncthreads();
    if (tid < 16) {
        float h = 0.f;
#pragma unroll
        for (int w = 0; w < 16; w++) h += part2[w][tid];
        g_H2[(size_t)row * 16 + tid] = h;
        float sa = h * __ldg(&a1o[tid]), sb = h * __ldg(&a2o[tid]);
#pragma unroll
        for (int o = 8; o > 0; o >>= 1) {
            sa += __shfl_xor_sync(0xffffu, sa, o, 16);
            sb += __shfl_xor_sync(0xffffu, sb, o, 16);
        }
        if (tid == 0) { g_s2[row] = sa; g_t2[row] = sb; }
    }
}

// ---------------- K3: output attention, warp-per-row ----------------
__global__ void __launch_bounds__(128) k_attn_out(const float* __restrict__ adj, float* __restrict__ out) {
    __shared__ float s_w[4][CAP];
    __shared__ int   s_ix[4][CAP];
    int w = threadIdx.x >> 5, lane = threadIdx.x & 31;
    int row = blockIdx.x * 4 + w;
    int cnt = g_cnt[row];
    float s_i = g_s2[row];
    bool sparse = (cnt > 0 && cnt <= CAP);

    if (sparse) {
        const int* nb = g_nbr + (size_t)row * CAP;
        float mx = -INFINITY;
        for (int k = lane; k < cnt; k += 32) {
            int ix = __ldg(&nb[k]);
            s_ix[w][k] = ix;
            float lv = lrelu(s_i + __ldg(&g_t2[ix]));
            s_w[w][k] = lv;
            mx = fmaxf(mx, lv);
        }
#pragma unroll
        for (int o = 16; o > 0; o >>= 1) mx = fmaxf(mx, __shfl_xor_sync(0xffffffffu, mx, o));
        float sum = 0.f;
        for (int k = lane; k < cnt; k += 32) {
            float e = __expf(s_w[w][k] - mx);
            s_w[w][k] = e;
            sum += e;
        }
#pragma unroll
        for (int o = 16; o > 0; o >>= 1) sum += __shfl_xor_sync(0xffffffffu, sum, o);
        __syncwarp();
        int q = lane >> 4, c = lane & 15;
        float acc = 0.f;
        int k = q;
        for (; k + 6 < cnt; k += 8) {
            float w0 = s_w[w][k],     w1 = s_w[w][k + 2];
            float w2 = s_w[w][k + 4], w3 = s_w[w][k + 6];
            int i0 = s_ix[w][k],     i1 = s_ix[w][k + 2];
            int i2 = s_ix[w][k + 4], i3 = s_ix[w][k + 6];
            float v0 = __ldg(&g_H2[(size_t)i0 * 16 + c]);
            float v1 = __ldg(&g_H2[(size_t)i1 * 16 + c]);
            float v2 = __ldg(&g_H2[(size_t)i2 * 16 + c]);
            float v3 = __ldg(&g_H2[(size_t)i3 * 16 + c]);
            acc += w0 * v0 + w1 * v1 + w2 * v2 + w3 * v3;
        }
        for (; k < cnt; k += 2)
            acc += s_w[w][k] * __ldg(&g_H2[(size_t)s_ix[w][k] * 16 + c]);
        acc += __shfl_down_sync(0xffffffffu, acc, 16);
        float v = eluf(acc / sum);
        float m16 = v;
#pragma unroll
        for (int o = 8; o > 0; o >>= 1) m16 = fmaxf(m16, __shfl_xor_sync(0xffffffffu, m16, o, 16));
        float e = __expf(v - m16);
        float se = e;
#pragma unroll
        for (int o = 8; o > 0; o >>= 1) se += __shfl_xor_sync(0xffffffffu, se, o, 16);
        if (lane < 16) out[(size_t)row * 16 + lane] = e / se;
    } else {
        const float* arow = adj + (size_t)row * NV;
        float mx = -INFINITY;
        for (int j = lane; j < NV; j += 32) {
            float lv = lrelu(s_i + g_t2[j]);
            if (arow[j] == 0.f) lv += NEGV;
            mx = fmaxf(mx, lv);
        }
#pragma unroll
        for (int o = 16; o > 0; o >>= 1) mx = fmaxf(mx, __shfl_xor_sync(0xffffffffu, mx, o));
        float sum = 0.f;
        for (int j = lane; j < NV; j += 32) {
            float lv = lrelu(s_i + g_t2[j]);
            if (arow[j] == 0.f) lv += NEGV;
            sum += __expf(lv - mx);
        }
#pragma unroll
        for (int o = 16; o > 0; o >>= 1) sum += __shfl_xor_sync(0xffffffffu, sum, o);
        int q = lane >> 4, c = lane & 15;
        float acc = 0.f;
        for (int j = q; j < NV; j += 2) {
            float lv = lrelu(s_i + g_t2[j]);
            if (arow[j] == 0.f) lv += NEGV;
            acc += __expf(lv - mx) * __ldg(&g_H2[(size_t)j * 16 + c]);
        }
        acc += __shfl_down_sync(0xffffffffu, acc, 16);
        float v = eluf(acc / sum);
        float m16 = v;
#pragma unroll
        for (int o = 8; o > 0; o >>= 1) m16 = fmaxf(m16, __shfl_xor_sync(0xffffffffu, m16, o, 16));
        float e = __expf(v - m16);
        float se = e;
#pragma unroll
        for (int o = 8; o > 0; o >>= 1) se += __shfl_xor_sync(0xffffffffu, se, o, 16);
        if (lane < 16) out[(size_t)row * 16 + lane] = e / se;
    }
}

// ---------------- launch ----------------
extern "C" void kernel_launch(void* const* d_in, const int* in_sizes, int n_in,
                              void* d_out, int out_size) {
    const float* adj  = (const float*)d_in[0];
    const float* feat = (const float*)d_in[1];
    const float* W0   = (const float*)d_in[2];
    const float* a1_0 = (const float*)d_in[3];
    const float* a2_0 = (const float*)d_in[4];
    const float* Wout = (const float*)d_in[5];
    const float* a1o  = (const float*)d_in[6];
    const float* a2o  = (const float*)d_in[7];
    float* out = (float*)d_out;

    k_gemm<<<(NV / 64) * NHEAD, 256>>>(feat, W0, a1_0, a2_0);   // tensor-core GEMM
    k_attn_hidden<<<NV, 256>>>(adj, Wout, a1o, a2o);            // adj scan fused
    k_attn_out<<<NV / 4, 128>>>(adj, out);
}